// round 1
// baseline (speedup 1.0000x reference)
#include <cuda_runtime.h>
#include <math.h>

// Problem dims
#define BB   512
#define SS   6
#define S2D  32
#define HH   256
#define NHH  8
#define HDD  32
#define DFF  2048
#define NLL  3
#define ROWS  (BB*SS)   // 3072
#define AROWS (BB*S2D)  // 16384

// ---------------- device scratch (no allocations allowed) ----------------
__device__ float g_x[ROWS*HH];
__device__ float g_qkv[ROWS*3*HH];
__device__ float g_ctx[ROWS*HH];
__device__ float g_sa[ROWS*HH];
__device__ float g_h[ROWS*DFF];
__device__ float g_U[AROWS*HH];
__device__ float g_V2[ROWS*HH];
__device__ float g_sf[AROWS*HH];
__device__ float g_sfm[BB*HH];
__device__ float g_aw[(size_t)NLL*AROWS*HH];
__device__ float g_adv[AROWS*NLL];
__device__ float g_val[BB];

// ---------------- helpers ----------------
__device__ __forceinline__ float block_reduce_sum(float v) {
    __shared__ float sm[33];
    int lane = threadIdx.x & 31, wid = threadIdx.x >> 5;
    __syncthreads();  // protect smem reuse across consecutive calls
    #pragma unroll
    for (int o = 16; o; o >>= 1) v += __shfl_down_sync(0xffffffffu, v, o);
    if (lane == 0) sm[wid] = v;
    __syncthreads();
    int nw = (blockDim.x + 31) >> 5;
    v = (threadIdx.x < nw) ? sm[threadIdx.x] : 0.f;
    if (wid == 0) {
        #pragma unroll
        for (int o = 16; o; o >>= 1) v += __shfl_down_sync(0xffffffffu, v, o);
        if (lane == 0) sm[32] = v;
    }
    __syncthreads();
    return sm[32];
}

// ---------------- positional encoding + add ----------------
__global__ void add_pe_kernel(const float* __restrict__ states, float* __restrict__ x) {
    int row = blockIdx.x;          // l*6 + n
    int e = threadIdx.x;
    int n = row % SS;
    int p = e >> 1;
    float div = expf(-(float)(2 * p) * (9.210340371976184f / 256.f));
    float ang = (float)n * div;
    float pe = (e & 1) ? cosf(ang) : sinf(ang);
    x[(size_t)row * HH + e] = states[(size_t)row * HH + e] + pe;
}

// ---------------- generic tiled fp32 GEMM ----------------
// C[M,N] = A[M,K] (row-major) x B
//   TRANSB=true : B stored [N, ldb] row-major, uses B[n*ldb + k]  (C = A @ B^T)
//   TRANSB=false: B stored [K, ldb] row-major, uses B[k*ldb + n]  (C = A @ B)
// All M, N multiples of 64, K multiple of 16 here (no bounds checks).
template<bool TRANSB, bool RELU>
__global__ __launch_bounds__(256) void gemm_kernel(
    const float* __restrict__ A, const float* __restrict__ B,
    const float* __restrict__ bias, float* __restrict__ C,
    int M, int N, int K, int ldb)
{
    __shared__ __align__(16) float As[16][68];
    __shared__ __align__(16) float Bs[16][68];
    int m0 = blockIdx.y * 64, n0 = blockIdx.x * 64;
    int t = threadIdx.x;
    int tx = t & 15, ty = t >> 4;
    float acc[4][4] = {};
    for (int k0 = 0; k0 < K; k0 += 16) {
        {   // A tile load (transposed into smem)
            int r = t >> 2, c = (t & 3) << 2;
            float4 v = *(const float4*)(A + (size_t)(m0 + r) * K + k0 + c);
            As[c + 0][r] = v.x; As[c + 1][r] = v.y; As[c + 2][r] = v.z; As[c + 3][r] = v.w;
        }
        if (TRANSB) {
            int r = t >> 2, c = (t & 3) << 2;
            float4 v = *(const float4*)(B + (size_t)(n0 + r) * ldb + k0 + c);
            Bs[c + 0][r] = v.x; Bs[c + 1][r] = v.y; Bs[c + 2][r] = v.z; Bs[c + 3][r] = v.w;
        } else {
            int r = t >> 4, c = (t & 15) << 2;
            float4 v = *(const float4*)(B + (size_t)(k0 + r) * ldb + n0 + c);
            *(float4*)&Bs[r][c] = v;
        }
        __syncthreads();
        #pragma unroll
        for (int kk = 0; kk < 16; kk++) {
            float4 a4 = *(const float4*)&As[kk][ty << 2];
            float4 b4 = *(const float4*)&Bs[kk][tx << 2];
            float av[4] = {a4.x, a4.y, a4.z, a4.w};
            float bv[4] = {b4.x, b4.y, b4.z, b4.w};
            #pragma unroll
            for (int i = 0; i < 4; i++)
                #pragma unroll
                for (int j = 0; j < 4; j++)
                    acc[i][j] = fmaf(av[i], bv[j], acc[i][j]);
        }
        __syncthreads();
    }
    #pragma unroll
    for (int i = 0; i < 4; i++) {
        int row = m0 + (ty << 2) + i;
        #pragma unroll
        for (int j = 0; j < 4; j++) {
            int col = n0 + (tx << 2) + j;
            float v = acc[i][j];
            if (bias) v += bias[col];
            if (RELU) v = fmaxf(v, 0.f);
            C[(size_t)row * N + col] = v;
        }
    }
}

// ---------------- attention over batch axis (flash style, 1 row/thread) ---
__global__ __launch_bounds__(128) void attn_kernel(const float* __restrict__ qkv,
                                                   float* __restrict__ ctx)
{
    __shared__ __align__(16) float Ks[128 * 32];
    __shared__ __align__(16) float Vs[128 * 32];
    int n = blockIdx.x >> 3, h = blockIdx.x & 7;
    int l = blockIdx.y * 128 + threadIdx.x;
    int qoff = h * 32;

    float q[32];
    {
        const float* qr = qkv + (size_t)(l * SS + n) * (3 * HH) + qoff;
        #pragma unroll
        for (int j = 0; j < 8; j++) {
            float4 v = *(const float4*)(qr + j * 4);
            q[j * 4 + 0] = v.x; q[j * 4 + 1] = v.y; q[j * 4 + 2] = v.z; q[j * 4 + 3] = v.w;
        }
    }

    float rm = -1e30f, rs = 0.f;
    float acc[32] = {};
    for (int m0 = 0; m0 < BB; m0 += 128) {
        __syncthreads();
        for (int i = threadIdx.x; i < 128 * 8; i += 128) {
            int mm = i >> 3, j = i & 7;
            const float* base = qkv + (size_t)((m0 + mm) * SS + n) * (3 * HH) + qoff;
            *(float4*)&Ks[mm * 32 + j * 4] = *(const float4*)(base + HH + j * 4);
            *(float4*)&Vs[mm * 32 + j * 4] = *(const float4*)(base + 2 * HH + j * 4);
        }
        __syncthreads();
        for (int mm = 0; mm < 128; mm++) {
            float s = 0.f;
            #pragma unroll
            for (int d = 0; d < 32; d++) s = fmaf(q[d], Ks[mm * 32 + d], s);
            s *= 0.17677669529663687f;  // 1/sqrt(32)
            if (s > rm) {
                float f = __expf(rm - s);
                rs *= f;
                #pragma unroll
                for (int d = 0; d < 32; d++) acc[d] *= f;
                rm = s;
            }
            float p = __expf(s - rm);
            rs += p;
            #pragma unroll
            for (int d = 0; d < 32; d++) acc[d] = fmaf(p, Vs[mm * 32 + d], acc[d]);
        }
    }
    float inv = 1.f / rs;
    float* cr = ctx + (size_t)(l * SS + n) * HH + qoff;
    #pragma unroll
    for (int d = 0; d < 32; d++) cr[d] = acc[d] * inv;
}

// ---------------- residual + layernorm (in place on x) ----------------
__global__ void ln_kernel(float* __restrict__ x, const float* __restrict__ delta,
                          const float* __restrict__ g, const float* __restrict__ b)
{
    int row = blockIdx.x, j = threadIdx.x;
    size_t idx = (size_t)row * HH + j;
    float v = x[idx] + delta[idx];
    float mu = block_reduce_sum(v) * (1.f / HH);
    float d = v - mu;
    float var = block_reduce_sum(d * d) * (1.f / HH);
    x[idx] = d * rsqrtf(var + 1e-5f) * g[j] + b[j];
}

// ---------------- fused attention-aggregate ----------------
// block = b*32+q (16384 blocks), 256 threads (one per hidden dim h).
// U already contains ba1 (folded at GEMM bias).
__global__ __launch_bounds__(256) void aggregate_kernel(
    const float* __restrict__ U, const float* __restrict__ V2,
    const float* __restrict__ outx, const float* __restrict__ Wa2,
    const float* __restrict__ ba2, const float* __restrict__ amask,
    const float* __restrict__ smask, float* __restrict__ sf)
{
    int b = blockIdx.x >> 5;
    int h = threadIdx.x;
    __shared__ float V2s[SS * HH];
    __shared__ float red[SS][8];
    __shared__ float wsh[SS];
    for (int i = h; i < SS * HH; i += 256) V2s[i] = V2[(size_t)b * SS * HH + i];
    __syncthreads();
    float u = U[(size_t)blockIdx.x * HH + h];
    float w2 = Wa2[h];
    float part[SS];
    #pragma unroll
    for (int k = 0; k < SS; k++) part[k] = w2 * fmaxf(u + V2s[k * HH + h], 0.f);
    int lane = h & 31, wid = h >> 5;
    #pragma unroll
    for (int k = 0; k < SS; k++) {
        float v = part[k];
        #pragma unroll
        for (int o = 16; o; o >>= 1) v += __shfl_down_sync(0xffffffffu, v, o);
        if (lane == 0) red[k][wid] = v;
    }
    __syncthreads();
    if (h < SS) {
        float s = 0.f;
        #pragma unroll
        for (int w = 0; w < 8; w++) s += red[h][w];
        float a = fmaxf(s + ba2[0], 0.f);
        float m = amask[blockIdx.x] * smask[b * SS + h];
        wsh[h] = (m > 0.f) ? __expf(a) : 0.f;
    }
    __syncthreads();
    float denom = wsh[0] + wsh[1] + wsh[2] + wsh[3] + wsh[4] + wsh[5];
    denom = fmaxf(denom, 2e-15f);
    float acc = 0.f;
    #pragma unroll
    for (int k = 0; k < SS; k++) acc = fmaf(wsh[k], outx[(size_t)(b * SS + k) * HH + h], acc);
    sf[(size_t)blockIdx.x * HH + h] = acc / denom;
}

// ---------------- states_feat mean over q ----------------
__global__ void sfm_kernel(const float* __restrict__ sf, const float* __restrict__ amask,
                           float* __restrict__ sfm)
{
    int b = blockIdx.x, j = threadIdx.x;
    float an = 0.f;
    for (int s = 0; s < S2D; s++) an += amask[b * S2D + s];
    float acc = 0.f;
    for (int s = 0; s < S2D; s++) acc += sf[(size_t)(b * S2D + s) * HH + j];
    sfm[(size_t)b * HH + j] = acc / an;
}

// ---------------- adv[b,s,l] = dot(aw, sf) + blab ----------------
__global__ void adv_kernel(const float* __restrict__ aw, const float* __restrict__ sf,
                           const float* __restrict__ blab, float* __restrict__ adv)
{
    int row = blockIdx.x, l = blockIdx.y;
    float v = aw[((size_t)l * AROWS + row) * HH + threadIdx.x] *
              sf[(size_t)row * HH + threadIdx.x];
    float s = block_reduce_sum(v);
    if (threadIdx.x == 0) adv[(size_t)row * NLL + l] = s + blab[l];
}

// ---------------- value head ----------------
__global__ void val_kernel(const float* __restrict__ sfm, const float* __restrict__ Wv,
                           const float* __restrict__ bv, float* __restrict__ val)
{
    int b = blockIdx.x;
    float v = sfm[(size_t)b * HH + threadIdx.x] * Wv[threadIdx.x];
    float s = block_reduce_sum(v);
    if (threadIdx.x == 0) val[b] = s + bv[0];
}

// ---------------- dueling combine + output ----------------
__global__ void final_kernel(const float* __restrict__ adv, const float* __restrict__ val,
                             float* __restrict__ out)
{
    int b = blockIdx.x, t = threadIdx.x;  // 128 threads, 96 active values
    float v = (t < S2D * NLL) ? adv[(size_t)b * S2D * NLL + t] : 0.f;
    float mean = block_reduce_sum(v) * (1.f / (S2D * NLL));
    if (t < S2D * NLL)
        out[(size_t)b * S2D * NLL + t] = val[b] + adv[(size_t)b * S2D * NLL + t] - mean;
}

// ---------------- launch ----------------
extern "C" void kernel_launch(void* const* d_in, const int* in_sizes, int n_in,
                              void* d_out, int out_size)
{
    const float* states = (const float*)d_in[0];
    const float* smask  = (const float*)d_in[1];
    const float* actions= (const float*)d_in[2];
    const float* amask  = (const float*)d_in[3];
    const float* Wqkv   = (const float*)d_in[4];
    const float* bqkv   = (const float*)d_in[5];
    const float* Wo     = (const float*)d_in[6];
    const float* bo     = (const float*)d_in[7];
    const float* ln1g   = (const float*)d_in[8];
    const float* ln1b   = (const float*)d_in[9];
    const float* W1     = (const float*)d_in[10];
    const float* b1     = (const float*)d_in[11];
    const float* W2     = (const float*)d_in[12];
    const float* b2     = (const float*)d_in[13];
    const float* ln2g   = (const float*)d_in[14];
    const float* ln2b   = (const float*)d_in[15];
    const float* Wa1    = (const float*)d_in[16];
    const float* ba1    = (const float*)d_in[17];
    const float* Wa2    = (const float*)d_in[18];
    const float* ba2    = (const float*)d_in[19];
    const float* Wv     = (const float*)d_in[20];
    const float* bv     = (const float*)d_in[21];
    const float* Wlab   = (const float*)d_in[22];
    const float* blab   = (const float*)d_in[23];
    float* out = (float*)d_out;

    float *px, *pqkv, *pctx, *psa, *ph, *pU, *pV2, *psf, *psfm, *paw, *padv, *pval;
    cudaGetSymbolAddress((void**)&px,   g_x);
    cudaGetSymbolAddress((void**)&pqkv, g_qkv);
    cudaGetSymbolAddress((void**)&pctx, g_ctx);
    cudaGetSymbolAddress((void**)&psa,  g_sa);
    cudaGetSymbolAddress((void**)&ph,   g_h);
    cudaGetSymbolAddress((void**)&pU,   g_U);
    cudaGetSymbolAddress((void**)&pV2,  g_V2);
    cudaGetSymbolAddress((void**)&psf,  g_sf);
    cudaGetSymbolAddress((void**)&psfm, g_sfm);
    cudaGetSymbolAddress((void**)&paw,  g_aw);
    cudaGetSymbolAddress((void**)&padv, g_adv);
    cudaGetSymbolAddress((void**)&pval, g_val);

    add_pe_kernel<<<ROWS, HH>>>(states, px);

    for (int i = 0; i < 3; i++) {
        gemm_kernel<true, false><<<dim3(768 / 64, ROWS / 64), 256>>>(
            px, Wqkv + (size_t)i * 3 * HH * HH, bqkv + (size_t)i * 3 * HH, pqkv,
            ROWS, 3 * HH, HH, HH);
        attn_kernel<<<dim3(SS * NHH, BB / 128), 128>>>(pqkv, pctx);
        gemm_kernel<true, false><<<dim3(HH / 64, ROWS / 64), 256>>>(
            pctx, Wo + (size_t)i * HH * HH, bo + (size_t)i * HH, psa,
            ROWS, HH, HH, HH);
        ln_kernel<<<ROWS, HH>>>(px, psa, ln1g + i * HH, ln1b + i * HH);
        gemm_kernel<true, true><<<dim3(DFF / 64, ROWS / 64), 256>>>(
            px, W1 + (size_t)i * DFF * HH, b1 + (size_t)i * DFF, ph,
            ROWS, DFF, HH, HH);
        gemm_kernel<true, false><<<dim3(HH / 64, ROWS / 64), 256>>>(
            ph, W2 + (size_t)i * HH * DFF, b2 + (size_t)i * HH, psa,
            ROWS, HH, DFF, DFF);
        ln_kernel<<<ROWS, HH>>>(px, psa, ln2g + i * HH, ln2b + i * HH);
    }

    // factored aggregate MLP: U = actions @ Wa1[:, :H]^T + ba1 ; V2 = out @ Wa1[:, H:]^T
    gemm_kernel<true, false><<<dim3(HH / 64, AROWS / 64), 256>>>(
        actions, Wa1, ba1, pU, AROWS, HH, HH, 2 * HH);
    gemm_kernel<true, false><<<dim3(HH / 64, ROWS / 64), 256>>>(
        px, Wa1 + HH, nullptr, pV2, ROWS, HH, HH, 2 * HH);

    aggregate_kernel<<<AROWS, HH>>>(pU, pV2, px, Wa2, ba2, amask, smask, psf);
    sfm_kernel<<<BB, HH>>>(psf, amask, psfm);

    // bilinear head: aw[l] = actions @ Wlab[l]
    for (int l = 0; l < NLL; l++)
        gemm_kernel<false, false><<<dim3(HH / 64, AROWS / 64), 256>>>(
            actions, Wlab + (size_t)l * HH * HH, nullptr,
            paw + (size_t)l * AROWS * HH, AROWS, HH, HH, HH);

    adv_kernel<<<dim3(AROWS, NLL), HH>>>(paw, psf, blab, padv);
    val_kernel<<<BB, HH>>>(psfm, Wv, bv, pval);
    final_kernel<<<BB, 128>>>(padv, pval, out);
}

// round 10
// speedup vs baseline: 1.4917x; 1.4917x over previous
#include <cuda_runtime.h>
#include <cuda_bf16.h>
#include <mma.h>
#include <math.h>

#define BB   512
#define SS   6
#define S2D  32
#define HH   256
#define NHH  8
#define DFF  2048
#define NLL  3
#define ROWS  (BB*SS)
#define AROWS (BB*S2D)
#define PITCH 40

using namespace nvcuda;

__device__ float g_x[ROWS*HH];
__device__ float g_qkv[ROWS*3*HH];
__device__ float g_ctx[ROWS*HH];
__device__ float g_sa[ROWS*HH];
__device__ float g_h[ROWS*DFF];
__device__ float g_U[AROWS*HH];
__device__ float g_V2[ROWS*HH];
__device__ float g_sf[AROWS*HH];
__device__ float g_sfm[BB*HH];
__device__ float g_aw[(size_t)NLL*AROWS*HH];
__device__ float g_adv[AROWS*NLL];
__device__ float g_val[BB];

__device__ __forceinline__ float block_reduce_sum(float v)
{
    __shared__ float sm[33];
    int lane = threadIdx.x & 31;
    int wid = threadIdx.x >> 5;
    __syncthreads();
    #pragma unroll
    for (int o = 16; o; o >>= 1) v += __shfl_down_sync(0xffffffffu, v, o);
    if (lane == 0) sm[wid] = v;
    __syncthreads();
    int nw = (blockDim.x + 31) >> 5;
    v = (threadIdx.x < nw) ? sm[threadIdx.x] : 0.f;
    if (wid == 0) {
        #pragma unroll
        for (int o = 16; o; o >>= 1) v += __shfl_down_sync(0xffffffffu, v, o);
        if (lane == 0) sm[32] = v;
    }
    __syncthreads();
    return sm[32];
}

__device__ __forceinline__ void cvt_hilo(float x, __nv_bfloat16& h, __nv_bfloat16& l)
{
    h = __float2bfloat16(x);
    l = __float2bfloat16(x - __bfloat162float(h));
}

__global__ void add_pe_kernel(const float* __restrict__ states, float* __restrict__ x)
{
    int row = blockIdx.x;
    int e = threadIdx.x;
    int n = row - (row / SS) * SS;
    int p = e >> 1;
    float dv = expf(-(float)(2 * p) * (9.210340371976184f / 256.f));
    float ang = (float)n * dv;
    float pe = (e & 1) ? cosf(ang) : sinf(ang);
    x[(size_t)row * HH + e] = states[(size_t)row * HH + e] + pe;
}

// bf16x3 tensor-core GEMM via WMMA: C[M,N] = A[M,K] @ B^T (B stored [N,ldb] row-major).
// Block tile 128x64, BK=32, 8 warps (4m x 2n), warp tile 32x32 as 2x2 wmma tiles.
// Requires M mult of 128, N mult of 64, K mult of 32.
template<bool RELU>
__global__ __launch_bounds__(256) void gemm3_kernel(
    const float* __restrict__ A, const float* __restrict__ Bg,
    const float* __restrict__ bias, float* __restrict__ Cg,
    int M, int N, int K, int ldb, size_t strideB, size_t strideC)
{
    const float* B = Bg + (size_t)blockIdx.z * strideB;
    float* C = Cg + (size_t)blockIdx.z * strideC;

    __shared__ __nv_bfloat16 Ah[128 * PITCH];
    __shared__ __nv_bfloat16 Al[128 * PITCH];
    __shared__ __nv_bfloat16 Bh[64 * PITCH];
    __shared__ __nv_bfloat16 Bl[64 * PITCH];
    __shared__ float Stage[8][16 * 20];

    int m0 = blockIdx.y * 128;
    int n0 = blockIdx.x * 64;
    int t = threadIdx.x;
    int warp = t >> 5;
    int lane = t & 31;
    int wm = warp >> 1;
    int wn = warp & 1;

    wmma::fragment<wmma::accumulator, 16, 16, 16, float> acc[2][2];
    #pragma unroll
    for (int mt = 0; mt < 2; mt++)
        #pragma unroll
        for (int nt = 0; nt < 2; nt++)
            wmma::fill_fragment(acc[mt][nt], 0.f);

    for (int k0 = 0; k0 < K; k0 += 32) {
        __syncthreads();
        {
            int r = t >> 1;
            int c0 = (t & 1) * 16;
            const float* src = A + (size_t)(m0 + r) * K + k0 + c0;
            __nv_bfloat16* dh = &Ah[r * PITCH + c0];
            __nv_bfloat16* dl = &Al[r * PITCH + c0];
            #pragma unroll
            for (int i = 0; i < 4; i++) {
                float4 v = *(const float4*)(src + i * 4);
                __nv_bfloat16 h0, h1, h2, h3, l0, l1, l2, l3;
                cvt_hilo(v.x, h0, l0);
                cvt_hilo(v.y, h1, l1);
                cvt_hilo(v.z, h2, l2);
                cvt_hilo(v.w, h3, l3);
                *(__nv_bfloat162*)(dh + i * 4)     = __halves2bfloat162(h0, h1);
                *(__nv_bfloat162*)(dh + i * 4 + 2) = __halves2bfloat162(h2, h3);
                *(__nv_bfloat162*)(dl + i * 4)     = __halves2bfloat162(l0, l1);
                *(__nv_bfloat162*)(dl + i * 4 + 2) = __halves2bfloat162(l2, l3);
            }
        }
        {
            int r = t >> 2;
            int c0 = (t & 3) * 8;
            const float* src = B + (size_t)(n0 + r) * ldb + k0 + c0;
            __nv_bfloat16* dh = &Bh[r * PITCH + c0];
            __nv_bfloat16* dl = &Bl[r * PITCH + c0];
            #pragma unroll
            for (int i = 0; i < 2; i++) {
                float4 v = *(const float4*)(src + i * 4);
                __nv_bfloat16 h0, h1, h2, h3, l0, l1, l2, l3;
                cvt_hilo(v.x, h0, l0);
                cvt_hilo(v.y, h1, l1);
                cvt_hilo(v.z, h2, l2);
                cvt_hilo(v.w, h3, l3);
                *(__nv_bfloat162*)(dh + i * 4)     = __halves2bfloat162(h0, h1);
                *(__nv_bfloat162*)(dh + i * 4 + 2) = __halves2bfloat162(h2, h3);
                *(__nv_bfloat162*)(dl + i * 4)     = __halves2bfloat162(l0, l1);
                *(__nv_bfloat162*)(dl + i * 4 + 2) = __halves2bfloat162(l2, l3);
            }
        }
        __syncthreads();

        #pragma unroll
        for (int kk = 0; kk < 32; kk += 16) {
            wmma::fragment<wmma::matrix_a, 16, 16, 16, __nv_bfloat16, wmma::row_major> fah[2], fal[2];
            wmma::fragment<wmma::matrix_b, 16, 16, 16, __nv_bfloat16, wmma::col_major> fbh[2], fbl[2];
            #pragma unroll
            for (int mt = 0; mt < 2; mt++) {
                int ar = wm * 32 + mt * 16;
                wmma::load_matrix_sync(fah[mt], &Ah[ar * PITCH + kk], PITCH);
                wmma::load_matrix_sync(fal[mt], &Al[ar * PITCH + kk], PITCH);
            }
            #pragma unroll
            for (int nt = 0; nt < 2; nt++) {
                int br = wn * 32 + nt * 16;
                wmma::load_matrix_sync(fbh[nt], &Bh[br * PITCH + kk], PITCH);
                wmma::load_matrix_sync(fbl[nt], &Bl[br * PITCH + kk], PITCH);
            }
            #pragma unroll
            for (int mt = 0; mt < 2; mt++) {
                #pragma unroll
                for (int nt = 0; nt < 2; nt++) {
                    wmma::mma_sync(acc[mt][nt], fah[mt], fbh[nt], acc[mt][nt]);
                    wmma::mma_sync(acc[mt][nt], fah[mt], fbl[nt], acc[mt][nt]);
                    wmma::mma_sync(acc[mt][nt], fal[mt], fbh[nt], acc[mt][nt]);
                }
            }
        }
    }

    #pragma unroll
    for (int mt = 0; mt < 2; mt++) {
        #pragma unroll
        for (int nt = 0; nt < 2; nt++) {
            wmma::store_matrix_sync(&Stage[warp][0], acc[mt][nt], 20, wmma::mem_row_major);
            __syncwarp();
            #pragma unroll
            for (int e = 0; e < 8; e++) {
                int idx = e * 32 + lane;
                int r = idx >> 4;
                int c = idx & 15;
                int row = m0 + wm * 32 + mt * 16 + r;
                int col = n0 + wn * 32 + nt * 16 + c;
                float v = Stage[warp][r * 20 + c];
                if (bias) v += bias[col];
                if (RELU) v = fmaxf(v, 0.f);
                C[(size_t)row * N + col] = v;
            }
            __syncwarp();
        }
    }
}

__global__ __launch_bounds__(128) void attn_kernel(const float* __restrict__ qkv,
                                                   float* __restrict__ ctx)
{
    __shared__ __align__(16) float Ks[128 * 32];
    __shared__ __align__(16) float Vs[128 * 32];
    int n = blockIdx.x >> 3;
    int h = blockIdx.x & 7;
    int l = blockIdx.y * 128 + threadIdx.x;
    int qoff = h * 32;

    float q[32];
    {
        const float* qr = qkv + (size_t)(l * SS + n) * (3 * HH) + qoff;
        #pragma unroll
        for (int j = 0; j < 8; j++) {
            float4 v = *(const float4*)(qr + j * 4);
            q[j * 4 + 0] = v.x;
            q[j * 4 + 1] = v.y;
            q[j * 4 + 2] = v.z;
            q[j * 4 + 3] = v.w;
        }
    }

    float rm = -1e30f;
    float rs = 0.f;
    float acc[32];
    #pragma unroll
    for (int d = 0; d < 32; d++) acc[d] = 0.f;

    for (int m0 = 0; m0 < BB; m0 += 128) {
        __syncthreads();
        for (int i = threadIdx.x; i < 128 * 8; i += 128) {
            int mm = i >> 3;
            int j = i & 7;
            const float* base = qkv + (size_t)((m0 + mm) * SS + n) * (3 * HH) + qoff;
            *(float4*)&Ks[mm * 32 + j * 4] = *(const float4*)(base + HH + j * 4);
            *(float4*)&Vs[mm * 32 + j * 4] = *(const float4*)(base + 2 * HH + j * 4);
        }
        __syncthreads();
        for (int mm = 0; mm < 128; mm++) {
            float s = 0.f;
            #pragma unroll
            for (int d = 0; d < 32; d++) s = fmaf(q[d], Ks[mm * 32 + d], s);
            s *= 0.17677669529663687f;
            if (s > rm) {
                float f = __expf(rm - s);
                rs *= f;
                #pragma unroll
                for (int d = 0; d < 32; d++) acc[d] *= f;
                rm = s;
            }
            float p = __expf(s - rm);
            rs += p;
            #pragma unroll
            for (int d = 0; d < 32; d++) acc[d] = fmaf(p, Vs[mm * 32 + d], acc[d]);
        }
    }
    float inv = 1.f / rs;
    float* cr = ctx + (size_t)(l * SS + n) * HH + qoff;
    #pragma unroll
    for (int d = 0; d < 32; d++) cr[d] = acc[d] * inv;
}

__global__ void ln_kernel(float* __restrict__ x, const float* __restrict__ delta,
                          const float* __restrict__ g, const float* __restrict__ b)
{
    int row = blockIdx.x;
    int j = threadIdx.x;
    size_t idx = (size_t)row * HH + j;
    float v = x[idx] + delta[idx];
    float mu = block_reduce_sum(v) * (1.f / HH);
    float d = v - mu;
    float var = block_reduce_sum(d * d) * (1.f / HH);
    x[idx] = d * rsqrtf(var + 1e-5f) * g[j] + b[j];
}

__global__ __launch_bounds__(256) void aggregate_kernel(
    const float* __restrict__ U, const float* __restrict__ V2,
    const float* __restrict__ outx, const float* __restrict__ Wa2,
    const float* __restrict__ ba2, const float* __restrict__ amask,
    const float* __restrict__ smask, float* __restrict__ sf)
{
    int b = blockIdx.x >> 5;
    int h = threadIdx.x;
    __shared__ float V2s[SS * HH];
    __shared__ float red[SS][8];
    __shared__ float wsh[SS];
    for (int i = h; i < SS * HH; i += 256) V2s[i] = V2[(size_t)b * SS * HH + i];
    __syncthreads();
    float u = U[(size_t)blockIdx.x * HH + h];
    float w2 = Wa2[h];
    float part[SS];
    #pragma unroll
    for (int k = 0; k < SS; k++) part[k] = w2 * fmaxf(u + V2s[k * HH + h], 0.f);
    int lane = h & 31;
    int wid = h >> 5;
    #pragma unroll
    for (int k = 0; k < SS; k++) {
        float v = part[k];
        #pragma unroll
        for (int o = 16; o; o >>= 1) v += __shfl_down_sync(0xffffffffu, v, o);
        if (lane == 0) red[k][wid] = v;
    }
    __syncthreads();
    if (h < SS) {
        float s = 0.f;
        #pragma unroll
        for (int w = 0; w < 8; w++) s += red[h][w];
        float a = fmaxf(s + ba2[0], 0.f);
        float m = amask[blockIdx.x] * smask[b * SS + h];
        wsh[h] = (m > 0.f) ? __expf(a) : 0.f;
    }
    __syncthreads();
    float denom = wsh[0] + wsh[1] + wsh[2] + wsh[3] + wsh[4] + wsh[5];
    denom = fmaxf(denom, 2e-15f);
    float acc = 0.f;
    #pragma unroll
    for (int k = 0; k < SS; k++) acc = fmaf(wsh[k], outx[(size_t)(b * SS + k) * HH + h], acc);
    sf[(size_t)blockIdx.x * HH + h] = acc / denom;
}

__global__ void sfm_kernel(const float* __restrict__ sf, const float* __restrict__ amask,
                           float* __restrict__ sfm)
{
    int b = blockIdx.x;
    int j = threadIdx.x;
    float an = 0.f;
    for (int s = 0; s < S2D; s++) an += amask[b * S2D + s];
    float acc = 0.f;
    for (int s = 0; s < S2D; s++) acc += sf[(size_t)(b * S2D + s) * HH + j];
    sfm[(size_t)b * HH + j] = acc / an;
}

__global__ void adv_kernel(const float* __restrict__ aw, const float* __restrict__ actions,
                           const float* __restrict__ blab, float* __restrict__ adv)
{
    int row = blockIdx.x;
    int l = blockIdx.y;
    float v = aw[((size_t)l * AROWS + row) * HH + threadIdx.x] *
              actions[(size_t)row * HH + threadIdx.x];
    float s = block_reduce_sum(v);
    if (threadIdx.x == 0) adv[(size_t)row * NLL + l] = s + blab[l];
}

__global__ void val_kernel(const float* __restrict__ sfm, const float* __restrict__ Wv,
                           const float* __restrict__ bv, float* __restrict__ val)
{
    int b = blockIdx.x;
    float v = sfm[(size_t)b * HH + threadIdx.x] * Wv[threadIdx.x];
    float s = block_reduce_sum(v);
    if (threadIdx.x == 0) val[b] = s + bv[0];
}

__global__ void final_kernel(const float* __restrict__ adv, const float* __restrict__ val,
                             float* __restrict__ out)
{
    int b = blockIdx.x;
    int t = threadIdx.x;
    float v = (t < S2D * NLL) ? adv[(size_t)b * S2D * NLL + t] : 0.f;
    float mean = block_reduce_sum(v) * (1.f / (S2D * NLL));
    if (t < S2D * NLL)
        out[(size_t)b * S2D * NLL + t] = val[b] + adv[(size_t)b * S2D * NLL + t] - mean;
}

extern "C" void kernel_launch(void* const* d_in, const int* in_sizes, int n_in,
                              void* d_out, int out_size)
{
    const float* states  = (const float*)d_in[0];
    const float* smask   = (const float*)d_in[1];
    const float* actions = (const float*)d_in[2];
    const float* amask   = (const float*)d_in[3];
    const float* Wqkv    = (const float*)d_in[4];
    const float* bqkv    = (const float*)d_in[5];
    const float* Wo      = (const float*)d_in[6];
    const float* bo      = (const float*)d_in[7];
    const float* ln1g    = (const float*)d_in[8];
    const float* ln1b    = (const float*)d_in[9];
    const float* W1      = (const float*)d_in[10];
    const float* b1      = (const float*)d_in[11];
    const float* W2      = (const float*)d_in[12];
    const float* b2      = (const float*)d_in[13];
    const float* ln2g    = (const float*)d_in[14];
    const float* ln2b    = (const float*)d_in[15];
    const float* Wa1     = (const float*)d_in[16];
    const float* ba1     = (const float*)d_in[17];
    const float* Wa2     = (const float*)d_in[18];
    const float* ba2     = (const float*)d_in[19];
    const float* Wv      = (const float*)d_in[20];
    const float* bv      = (const float*)d_in[21];
    const float* Wlab    = (const float*)d_in[22];
    const float* blab    = (const float*)d_in[23];
    float* out = (float*)d_out;

    float *px, *pqkv, *pctx, *psa, *ph, *pU, *pV2, *psf, *psfm, *paw, *padv, *pval;
    cudaGetSymbolAddress((void**)&px,   g_x);
    cudaGetSymbolAddress((void**)&pqkv, g_qkv);
    cudaGetSymbolAddress((void**)&pctx, g_ctx);
    cudaGetSymbolAddress((void**)&psa,  g_sa);
    cudaGetSymbolAddress((void**)&ph,   g_h);
    cudaGetSymbolAddress((void**)&pU,   g_U);
    cudaGetSymbolAddress((void**)&pV2,  g_V2);
    cudaGetSymbolAddress((void**)&psf,  g_sf);
    cudaGetSymbolAddress((void**)&psfm, g_sfm);
    cudaGetSymbolAddress((void**)&paw,  g_aw);
    cudaGetSymbolAddress((void**)&padv, g_adv);
    cudaGetSymbolAddress((void**)&pval, g_val);

    add_pe_kernel<<<ROWS, HH>>>(states, px);

    for (int i = 0; i < 3; i++) {
        gemm3_kernel<false><<<dim3(12, 24, 1), 256>>>(
            px, Wqkv + (size_t)i * 3 * HH * HH, bqkv + (size_t)i * 3 * HH, pqkv,
            ROWS, 3 * HH, HH, HH, 0, 0);
        attn_kernel<<<dim3(SS * NHH, BB / 128), 128>>>(pqkv, pctx);
        gemm3_kernel<false><<<dim3(4, 24, 1), 256>>>(
            pctx, Wo + (size_t)i * HH * HH, bo + (size_t)i * HH, psa,
            ROWS, HH, HH, HH, 0, 0);
        ln_kernel<<<ROWS, HH>>>(px, psa, ln1g + i * HH, ln1b + i * HH);
        gemm3_kernel<true><<<dim3(32, 24, 1), 256>>>(
            px, W1 + (size_t)i * DFF * HH, b1 + (size_t)i * DFF, ph,
            ROWS, DFF, HH, HH, 0, 0);
        gemm3_kernel<false><<<dim3(4, 24, 1), 256>>>(
            ph, W2 + (size_t)i * HH * DFF, b2 + (size_t)i * HH, psa,
            ROWS, HH, DFF, DFF, 0, 0);
        ln_kernel<<<ROWS, HH>>>(px, psa, ln2g + i * HH, ln2b + i * HH);
    }

    gemm3_kernel<false><<<dim3(4, 128, 1), 256>>>(
        actions, Wa1, ba1, pU, AROWS, HH, HH, 2 * HH, 0, 0);
    gemm3_kernel<false><<<dim3(4, 24, 1), 256>>>(
        px, Wa1 + HH, nullptr, pV2, ROWS, HH, HH, 2 * HH, 0, 0);

    aggregate_kernel<<<AROWS, HH>>>(pU, pV2, px, Wa2, ba2, amask, smask, psf);
    sfm_kernel<<<BB, HH>>>(psf, amask, psfm);

    gemm3_kernel<false><<<dim3(4, 128, NLL), 256>>>(
        psf, Wlab, nullptr, paw, AROWS, HH, HH, HH,
        (size_t)HH * HH, (size_t)AROWS * HH);

    adv_kernel<<<dim3(AROWS, NLL), HH>>>(paw, actions, blab, padv);
    val_kernel<<<BB, HH>>>(psfm, Wv, bv, pval);
    final_kernel<<<BB, 128>>>(padv, pval, out);
}

// round 11
// speedup vs baseline: 1.5319x; 1.0270x over previous
#include <cuda_runtime.h>
#include <cuda_bf16.h>
#include <mma.h>
#include <math.h>

#define BB   512
#define SS   6
#define S2D  32
#define HH   256
#define NHH  8
#define DFF  2048
#define NLL  3
#define ROWS  (BB*SS)
#define AROWS (BB*S2D)
#define PITCH 40

using namespace nvcuda;

// fp32 scratch
__device__ float g_x[ROWS*HH];
__device__ float g_qkv[ROWS*3*HH];
__device__ float g_sa[ROWS*HH];
__device__ float g_U[AROWS*HH];
__device__ float g_V2[ROWS*HH];
__device__ float g_sf[AROWS*HH];
__device__ float g_sfm[BB*HH];
__device__ float g_aw[(size_t)NLL*AROWS*HH];
__device__ float g_adv[AROWS*NLL];
__device__ float g_val[BB];
__device__ float g_part[4*ROWS*HH];

// bf16 hi/lo activation copies
__device__ __nv_bfloat16 g_xh[ROWS*HH],     g_xl[ROWS*HH];
__device__ __nv_bfloat16 g_ctxh[ROWS*HH],   g_ctxl[ROWS*HH];
__device__ __nv_bfloat16 g_hh[ROWS*DFF],    g_hl[ROWS*DFF];
__device__ __nv_bfloat16 g_acth[AROWS*HH],  g_actl[AROWS*HH];
__device__ __nv_bfloat16 g_sfh[AROWS*HH],   g_sfl[AROWS*HH];

// bf16 hi/lo weight copies
__device__ __nv_bfloat16 g_wqkvh[3*3*HH*HH], g_wqkvl[3*3*HH*HH];
__device__ __nv_bfloat16 g_woh[3*HH*HH],     g_wol[3*HH*HH];
__device__ __nv_bfloat16 g_w1h[3*DFF*HH],    g_w1l[3*DFF*HH];
__device__ __nv_bfloat16 g_w2h[3*HH*DFF],    g_w2l[3*HH*DFF];
__device__ __nv_bfloat16 g_wa1h[HH*2*HH],    g_wa1l[HH*2*HH];
__device__ __nv_bfloat16 g_wlabh[NLL*HH*HH], g_wlabl[NLL*HH*HH];

__device__ __forceinline__ float block_reduce_sum(float v)
{
    __shared__ float sm[33];
    int lane = threadIdx.x & 31;
    int wid = threadIdx.x >> 5;
    __syncthreads();
    #pragma unroll
    for (int o = 16; o; o >>= 1) v += __shfl_down_sync(0xffffffffu, v, o);
    if (lane == 0) sm[wid] = v;
    __syncthreads();
    int nw = (blockDim.x + 31) >> 5;
    v = (threadIdx.x < nw) ? sm[threadIdx.x] : 0.f;
    if (wid == 0) {
        #pragma unroll
        for (int o = 16; o; o >>= 1) v += __shfl_down_sync(0xffffffffu, v, o);
        if (lane == 0) sm[32] = v;
    }
    __syncthreads();
    return sm[32];
}

__device__ __forceinline__ void cvt_hilo(float x, __nv_bfloat16& h, __nv_bfloat16& l)
{
    h = __float2bfloat16(x);
    l = __float2bfloat16(x - __bfloat162float(h));
}

// elementwise fp32 -> (hi, lo) bf16
__global__ void cvt_kernel(const float* __restrict__ in,
                           __nv_bfloat16* __restrict__ h,
                           __nv_bfloat16* __restrict__ l, int n)
{
    int i = blockIdx.x * 256 + threadIdx.x;
    if (i < n) {
        __nv_bfloat16 hh, ll;
        cvt_hilo(in[i], hh, ll);
        h[i] = hh;
        l[i] = ll;
    }
}

__global__ void add_pe_kernel(const float* __restrict__ states, float* __restrict__ x,
                              __nv_bfloat16* __restrict__ xh, __nv_bfloat16* __restrict__ xl)
{
    int row = blockIdx.x;
    int e = threadIdx.x;
    int n = row - (row / SS) * SS;
    int p = e >> 1;
    float dv = expf(-(float)(2 * p) * (9.210340371976184f / 256.f));
    float ang = (float)n * dv;
    float pe = (e & 1) ? cosf(ang) : sinf(ang);
    size_t idx = (size_t)row * HH + e;
    float v = states[idx] + pe;
    x[idx] = v;
    __nv_bfloat16 hh, ll;
    cvt_hilo(v, hh, ll);
    xh[idx] = hh;
    xl[idx] = ll;
}

// bf16x3 WMMA GEMM on pre-split inputs.
// C[M,N] = A[M,lda-rows...] @ B^T ; A row-major (lda), B [N,ldb] row-major.
// Block tile 128x64, BK=32, 8 warps (4m x 2n).
// blockIdx.z: k-split chunk (kPerZ>0) OR batched B/C (strideBz/strideCz).
// OUTBF16: write hi/lo bf16 to Ch/Cl instead of fp32 C.
template<bool RELU, bool OUTBF16>
__global__ __launch_bounds__(256) void gemm3_kernel(
    const __nv_bfloat16* __restrict__ Ahg, const __nv_bfloat16* __restrict__ Alg,
    const __nv_bfloat16* __restrict__ Bhg, const __nv_bfloat16* __restrict__ Blg,
    const float* __restrict__ bias, float* __restrict__ C,
    __nv_bfloat16* __restrict__ Ch, __nv_bfloat16* __restrict__ Cl,
    int M, int N, int lda, int ldb, int kLen, int kPerZ,
    size_t strideBz, size_t strideCz)
{
    const __nv_bfloat16* Bh_p = Bhg + (size_t)blockIdx.z * strideBz;
    const __nv_bfloat16* Bl_p = Blg + (size_t)blockIdx.z * strideBz;
    size_t coff = (size_t)blockIdx.z * strideCz;
    int kOff = blockIdx.z * kPerZ;

    __shared__ __nv_bfloat16 Ahs[128 * PITCH];
    __shared__ __nv_bfloat16 Als[128 * PITCH];
    __shared__ __nv_bfloat16 Bhs[64 * PITCH];
    __shared__ __nv_bfloat16 Bls[64 * PITCH];
    __shared__ float Stage[8][16 * 20];

    int m0 = blockIdx.y * 128;
    int n0 = blockIdx.x * 64;
    int t = threadIdx.x;
    int warp = t >> 5;
    int lane = t & 31;
    int wm = warp >> 1;
    int wn = warp & 1;

    wmma::fragment<wmma::accumulator, 16, 16, 16, float> acc[2][2];
    #pragma unroll
    for (int mt = 0; mt < 2; mt++)
        #pragma unroll
        for (int nt = 0; nt < 2; nt++)
            wmma::fill_fragment(acc[mt][nt], 0.f);

    for (int k0 = 0; k0 < kLen; k0 += 32) {
        int gk = kOff + k0;
        __syncthreads();
        {
            int c1 = t;
            int r1 = c1 >> 2;
            int cc1 = (c1 & 3) * 8;
            int c2 = t + 256;
            int r2 = c2 >> 2;
            int cc2 = (c2 & 3) * 8;
            *(float4*)&Ahs[r1 * PITCH + cc1] = *(const float4*)&Ahg[(size_t)(m0 + r1) * lda + gk + cc1];
            *(float4*)&Ahs[r2 * PITCH + cc2] = *(const float4*)&Ahg[(size_t)(m0 + r2) * lda + gk + cc2];
            *(float4*)&Als[r1 * PITCH + cc1] = *(const float4*)&Alg[(size_t)(m0 + r1) * lda + gk + cc1];
            *(float4*)&Als[r2 * PITCH + cc2] = *(const float4*)&Alg[(size_t)(m0 + r2) * lda + gk + cc2];
            int rb = t >> 2;
            int cb = (t & 3) * 8;
            *(float4*)&Bhs[rb * PITCH + cb] = *(const float4*)&Bh_p[(size_t)(n0 + rb) * ldb + gk + cb];
            *(float4*)&Bls[rb * PITCH + cb] = *(const float4*)&Bl_p[(size_t)(n0 + rb) * ldb + gk + cb];
        }
        __syncthreads();

        #pragma unroll
        for (int kk = 0; kk < 32; kk += 16) {
            wmma::fragment<wmma::matrix_a, 16, 16, 16, __nv_bfloat16, wmma::row_major> fah[2], fal[2];
            wmma::fragment<wmma::matrix_b, 16, 16, 16, __nv_bfloat16, wmma::col_major> fbh[2], fbl[2];
            #pragma unroll
            for (int mt = 0; mt < 2; mt++) {
                int ar = wm * 32 + mt * 16;
                wmma::load_matrix_sync(fah[mt], &Ahs[ar * PITCH + kk], PITCH);
                wmma::load_matrix_sync(fal[mt], &Als[ar * PITCH + kk], PITCH);
            }
            #pragma unroll
            for (int nt = 0; nt < 2; nt++) {
                int br = wn * 32 + nt * 16;
                wmma::load_matrix_sync(fbh[nt], &Bhs[br * PITCH + kk], PITCH);
                wmma::load_matrix_sync(fbl[nt], &Bls[br * PITCH + kk], PITCH);
            }
            #pragma unroll
            for (int mt = 0; mt < 2; mt++) {
                #pragma unroll
                for (int nt = 0; nt < 2; nt++) {
                    wmma::mma_sync(acc[mt][nt], fah[mt], fbh[nt], acc[mt][nt]);
                    wmma::mma_sync(acc[mt][nt], fah[mt], fbl[nt], acc[mt][nt]);
                    wmma::mma_sync(acc[mt][nt], fal[mt], fbh[nt], acc[mt][nt]);
                }
            }
        }
    }

    #pragma unroll
    for (int mt = 0; mt < 2; mt++) {
        #pragma unroll
        for (int nt = 0; nt < 2; nt++) {
            wmma::store_matrix_sync(&Stage[warp][0], acc[mt][nt], 20, wmma::mem_row_major);
            __syncwarp();
            #pragma unroll
            for (int e = 0; e < 8; e++) {
                int idx = e * 32 + lane;
                int r = idx >> 4;
                int c = idx & 15;
                int row = m0 + wm * 32 + mt * 16 + r;
                int col = n0 + wn * 32 + nt * 16 + c;
                float v = Stage[warp][r * 20 + c];
                if (bias) v += bias[col];
                if (RELU) v = fmaxf(v, 0.f);
                size_t oidx = coff + (size_t)row * N + col;
                if (OUTBF16) {
                    __nv_bfloat16 hh, ll;
                    cvt_hilo(v, hh, ll);
                    Ch[oidx] = hh;
                    Cl[oidx] = ll;
                } else {
                    C[oidx] = v;
                }
            }
            __syncwarp();
        }
    }
}

// reduce 4 split-K partials + bias
__global__ void reduce4_kernel(const float* __restrict__ part, const float* __restrict__ bias,
                               float* __restrict__ outp)
{
    int i = blockIdx.x * 256 + threadIdx.x;
    int col = i & (HH - 1);
    const int MN = ROWS * HH;
    float v = part[i] + part[i + MN] + part[i + 2 * MN] + part[i + 3 * MN] + bias[col];
    outp[i] = v;
}

__global__ __launch_bounds__(128) void attn_kernel(const float* __restrict__ qkv,
                                                   __nv_bfloat16* __restrict__ ctxh,
                                                   __nv_bfloat16* __restrict__ ctxl)
{
    __shared__ __align__(16) float Ks[128 * 32];
    __shared__ __align__(16) float Vs[128 * 32];
    int n = blockIdx.x >> 3;
    int h = blockIdx.x & 7;
    int l = blockIdx.y * 128 + threadIdx.x;
    int qoff = h * 32;

    float q[32];
    {
        const float* qr = qkv + (size_t)(l * SS + n) * (3 * HH) + qoff;
        #pragma unroll
        for (int j = 0; j < 8; j++) {
            float4 v = *(const float4*)(qr + j * 4);
            q[j * 4 + 0] = v.x;
            q[j * 4 + 1] = v.y;
            q[j * 4 + 2] = v.z;
            q[j * 4 + 3] = v.w;
        }
    }

    float rm = -1e30f;
    float rs = 0.f;
    float acc[32];
    #pragma unroll
    for (int d = 0; d < 32; d++) acc[d] = 0.f;

    for (int m0 = 0; m0 < BB; m0 += 128) {
        __syncthreads();
        for (int i = threadIdx.x; i < 128 * 8; i += 128) {
            int mm = i >> 3;
            int j = i & 7;
            const float* base = qkv + (size_t)((m0 + mm) * SS + n) * (3 * HH) + qoff;
            *(float4*)&Ks[mm * 32 + j * 4] = *(const float4*)(base + HH + j * 4);
            *(float4*)&Vs[mm * 32 + j * 4] = *(const float4*)(base + 2 * HH + j * 4);
        }
        __syncthreads();
        for (int mm = 0; mm < 128; mm++) {
            float s = 0.f;
            #pragma unroll
            for (int d = 0; d < 32; d++) s = fmaf(q[d], Ks[mm * 32 + d], s);
            s *= 0.17677669529663687f;
            if (s > rm) {
                float f = __expf(rm - s);
                rs *= f;
                #pragma unroll
                for (int d = 0; d < 32; d++) acc[d] *= f;
                rm = s;
            }
            float p = __expf(s - rm);
            rs += p;
            #pragma unroll
            for (int d = 0; d < 32; d++) acc[d] = fmaf(p, Vs[mm * 32 + d], acc[d]);
        }
    }
    float inv = 1.f / rs;
    size_t obase = (size_t)(l * SS + n) * HH + qoff;
    #pragma unroll
    for (int d = 0; d < 32; d++) {
        __nv_bfloat16 hh, ll;
        cvt_hilo(acc[d] * inv, hh, ll);
        ctxh[obase + d] = hh;
        ctxl[obase + d] = ll;
    }
}

__global__ void ln_kernel(float* __restrict__ x, const float* __restrict__ delta,
                          const float* __restrict__ g, const float* __restrict__ b,
                          __nv_bfloat16* __restrict__ xh, __nv_bfloat16* __restrict__ xl)
{
    int row = blockIdx.x;
    int j = threadIdx.x;
    size_t idx = (size_t)row * HH + j;
    float v = x[idx] + delta[idx];
    float mu = block_reduce_sum(v) * (1.f / HH);
    float d = v - mu;
    float var = block_reduce_sum(d * d) * (1.f / HH);
    float o = d * rsqrtf(var + 1e-5f) * g[j] + b[j];
    x[idx] = o;
    __nv_bfloat16 hh, ll;
    cvt_hilo(o, hh, ll);
    xh[idx] = hh;
    xl[idx] = ll;
}

__global__ __launch_bounds__(256) void aggregate_kernel(
    const float* __restrict__ U, const float* __restrict__ V2,
    const float* __restrict__ outx, const float* __restrict__ Wa2,
    const float* __restrict__ ba2, const float* __restrict__ amask,
    const float* __restrict__ smask, float* __restrict__ sf,
    __nv_bfloat16* __restrict__ sfh, __nv_bfloat16* __restrict__ sfl)
{
    int b = blockIdx.x >> 5;
    int h = threadIdx.x;
    __shared__ float V2s[SS * HH];
    __shared__ float red[SS][8];
    __shared__ float wsh[SS];
    for (int i = h; i < SS * HH; i += 256) V2s[i] = V2[(size_t)b * SS * HH + i];
    __syncthreads();
    float u = U[(size_t)blockIdx.x * HH + h];
    float w2 = Wa2[h];
    float part[SS];
    #pragma unroll
    for (int k = 0; k < SS; k++) part[k] = w2 * fmaxf(u + V2s[k * HH + h], 0.f);
    int lane = h & 31;
    int wid = h >> 5;
    #pragma unroll
    for (int k = 0; k < SS; k++) {
        float v = part[k];
        #pragma unroll
        for (int o = 16; o; o >>= 1) v += __shfl_down_sync(0xffffffffu, v, o);
        if (lane == 0) red[k][wid] = v;
    }
    __syncthreads();
    if (h < SS) {
        float s = 0.f;
        #pragma unroll
        for (int w = 0; w < 8; w++) s += red[h][w];
        float a = fmaxf(s + ba2[0], 0.f);
        float m = amask[blockIdx.x] * smask[b * SS + h];
        wsh[h] = (m > 0.f) ? __expf(a) : 0.f;
    }
    __syncthreads();
    float denom = wsh[0] + wsh[1] + wsh[2] + wsh[3] + wsh[4] + wsh[5];
    denom = fmaxf(denom, 2e-15f);
    float acc = 0.f;
    #pragma unroll
    for (int k = 0; k < SS; k++) acc = fmaf(wsh[k], outx[(size_t)(b * SS + k) * HH + h], acc);
    float o = acc / denom;
    size_t oidx = (size_t)blockIdx.x * HH + h;
    sf[oidx] = o;
    __nv_bfloat16 hh, ll;
    cvt_hilo(o, hh, ll);
    sfh[oidx] = hh;
    sfl[oidx] = ll;
}

__global__ void sfm_kernel(const float* __restrict__ sf, const float* __restrict__ amask,
                           float* __restrict__ sfm)
{
    int b = blockIdx.x;
    int j = threadIdx.x;
    float an = 0.f;
    for (int s = 0; s < S2D; s++) an += amask[b * S2D + s];
    float acc = 0.f;
    for (int s = 0; s < S2D; s++) acc += sf[(size_t)(b * S2D + s) * HH + j];
    sfm[(size_t)b * HH + j] = acc / an;
}

__global__ void adv_kernel(const float* __restrict__ aw, const float* __restrict__ actions,
                           const float* __restrict__ blab, float* __restrict__ adv)
{
    int row = blockIdx.x;
    int l = blockIdx.y;
    float v = aw[((size_t)l * AROWS + row) * HH + threadIdx.x] *
              actions[(size_t)row * HH + threadIdx.x];
    float s = block_reduce_sum(v);
    if (threadIdx.x == 0) adv[(size_t)row * NLL + l] = s + blab[l];
}

__global__ void val_kernel(const float* __restrict__ sfm, const float* __restrict__ Wv,
                           const float* __restrict__ bv, float* __restrict__ val)
{
    int b = blockIdx.x;
    float v = sfm[(size_t)b * HH + threadIdx.x] * Wv[threadIdx.x];
    float s = block_reduce_sum(v);
    if (threadIdx.x == 0) val[b] = s + bv[0];
}

__global__ void final_kernel(const float* __restrict__ adv, const float* __restrict__ val,
                             float* __restrict__ out)
{
    int b = blockIdx.x;
    int t = threadIdx.x;
    float v = (t < S2D * NLL) ? adv[(size_t)b * S2D * NLL + t] : 0.f;
    float mean = block_reduce_sum(v) * (1.f / (S2D * NLL));
    if (t < S2D * NLL)
        out[(size_t)b * S2D * NLL + t] = val[b] + adv[(size_t)b * S2D * NLL + t] - mean;
}

extern "C" void kernel_launch(void* const* d_in, const int* in_sizes, int n_in,
                              void* d_out, int out_size)
{
    const float* states  = (const float*)d_in[0];
    const float* smask   = (const float*)d_in[1];
    const float* actions = (const float*)d_in[2];
    const float* amask   = (const float*)d_in[3];
    const float* Wqkv    = (const float*)d_in[4];
    const float* bqkv    = (const float*)d_in[5];
    const float* Wo      = (const float*)d_in[6];
    const float* bo      = (const float*)d_in[7];
    const float* ln1g    = (const float*)d_in[8];
    const float* ln1b    = (const float*)d_in[9];
    const float* W1      = (const float*)d_in[10];
    const float* b1      = (const float*)d_in[11];
    const float* W2      = (const float*)d_in[12];
    const float* b2      = (const float*)d_in[13];
    const float* ln2g    = (const float*)d_in[14];
    const float* ln2b    = (const float*)d_in[15];
    const float* Wa1     = (const float*)d_in[16];
    const float* ba1     = (const float*)d_in[17];
    const float* Wa2     = (const float*)d_in[18];
    const float* ba2     = (const float*)d_in[19];
    const float* Wv      = (const float*)d_in[20];
    const float* bv      = (const float*)d_in[21];
    const float* Wlab    = (const float*)d_in[22];
    const float* blab    = (const float*)d_in[23];
    float* out = (float*)d_out;

    float *px, *pqkv, *psa, *pU, *pV2, *psf, *psfm, *paw, *padv, *pval, *ppart;
    cudaGetSymbolAddress((void**)&px,    g_x);
    cudaGetSymbolAddress((void**)&pqkv,  g_qkv);
    cudaGetSymbolAddress((void**)&psa,   g_sa);
    cudaGetSymbolAddress((void**)&pU,    g_U);
    cudaGetSymbolAddress((void**)&pV2,   g_V2);
    cudaGetSymbolAddress((void**)&psf,   g_sf);
    cudaGetSymbolAddress((void**)&psfm,  g_sfm);
    cudaGetSymbolAddress((void**)&paw,   g_aw);
    cudaGetSymbolAddress((void**)&padv,  g_adv);
    cudaGetSymbolAddress((void**)&pval,  g_val);
    cudaGetSymbolAddress((void**)&ppart, g_part);

    __nv_bfloat16 *pxh, *pxl, *pctxh, *pctxl, *phh, *phl, *pacth, *pactl, *psfh, *psfl;
    __nv_bfloat16 *pwqkvh, *pwqkvl, *pwoh, *pwol, *pw1h, *pw1l, *pw2h, *pw2l;
    __nv_bfloat16 *pwa1h, *pwa1l, *pwlabh, *pwlabl;
    cudaGetSymbolAddress((void**)&pxh,    g_xh);
    cudaGetSymbolAddress((void**)&pxl,    g_xl);
    cudaGetSymbolAddress((void**)&pctxh,  g_ctxh);
    cudaGetSymbolAddress((void**)&pctxl,  g_ctxl);
    cudaGetSymbolAddress((void**)&phh,    g_hh);
    cudaGetSymbolAddress((void**)&phl,    g_hl);
    cudaGetSymbolAddress((void**)&pacth,  g_acth);
    cudaGetSymbolAddress((void**)&pactl,  g_actl);
    cudaGetSymbolAddress((void**)&psfh,   g_sfh);
    cudaGetSymbolAddress((void**)&psfl,   g_sfl);
    cudaGetSymbolAddress((void**)&pwqkvh, g_wqkvh);
    cudaGetSymbolAddress((void**)&pwqkvl, g_wqkvl);
    cudaGetSymbolAddress((void**)&pwoh,   g_woh);
    cudaGetSymbolAddress((void**)&pwol,   g_wol);
    cudaGetSymbolAddress((void**)&pw1h,   g_w1h);
    cudaGetSymbolAddress((void**)&pw1l,   g_w1l);
    cudaGetSymbolAddress((void**)&pw2h,   g_w2h);
    cudaGetSymbolAddress((void**)&pw2l,   g_w2l);
    cudaGetSymbolAddress((void**)&pwa1h,  g_wa1h);
    cudaGetSymbolAddress((void**)&pwa1l,  g_wa1l);
    cudaGetSymbolAddress((void**)&pwlabh, g_wlabh);
    cudaGetSymbolAddress((void**)&pwlabl, g_wlabl);

    // weight + actions conversion (once per launch)
    {
        int n;
        n = 3 * 3 * HH * HH;  cvt_kernel<<<(n + 255) / 256, 256>>>(Wqkv,    pwqkvh, pwqkvl, n);
        n = 3 * HH * HH;      cvt_kernel<<<(n + 255) / 256, 256>>>(Wo,      pwoh,   pwol,   n);
        n = 3 * DFF * HH;     cvt_kernel<<<(n + 255) / 256, 256>>>(W1,      pw1h,   pw1l,   n);
        n = 3 * HH * DFF;     cvt_kernel<<<(n + 255) / 256, 256>>>(W2,      pw2h,   pw2l,   n);
        n = HH * 2 * HH;      cvt_kernel<<<(n + 255) / 256, 256>>>(Wa1,     pwa1h,  pwa1l,  n);
        n = NLL * HH * HH;    cvt_kernel<<<(n + 255) / 256, 256>>>(Wlab,    pwlabh, pwlabl, n);
        n = AROWS * HH;       cvt_kernel<<<(n + 255) / 256, 256>>>(actions, pacth,  pactl,  n);
    }

    add_pe_kernel<<<ROWS, HH>>>(states, px, pxh, pxl);

    for (int i = 0; i < 3; i++) {
        // QKV: [3072,768] = x @ Wqkv^T + bqkv
        gemm3_kernel<false, false><<<dim3(12, 24, 1), 256>>>(
            pxh, pxl, pwqkvh + (size_t)i * 3 * HH * HH, pwqkvl + (size_t)i * 3 * HH * HH,
            bqkv + (size_t)i * 3 * HH, pqkv, nullptr, nullptr,
            ROWS, 3 * HH, HH, HH, HH, 0, 0, 0);
        attn_kernel<<<dim3(SS * NHH, BB / 128), 128>>>(pqkv, pctxh, pctxl);
        gemm3_kernel<false, false><<<dim3(4, 24, 1), 256>>>(
            pctxh, pctxl, pwoh + (size_t)i * HH * HH, pwol + (size_t)i * HH * HH,
            bo + (size_t)i * HH, psa, nullptr, nullptr,
            ROWS, HH, HH, HH, HH, 0, 0, 0);
        ln_kernel<<<ROWS, HH>>>(px, psa, ln1g + i * HH, ln1b + i * HH, pxh, pxl);
        // W1: relu, bf16 hi/lo output
        gemm3_kernel<true, true><<<dim3(32, 24, 1), 256>>>(
            pxh, pxl, pw1h + (size_t)i * DFF * HH, pw1l + (size_t)i * DFF * HH,
            b1 + (size_t)i * DFF, nullptr, phh, phl,
            ROWS, DFF, HH, HH, HH, 0, 0, 0);
        // W2: split-K 4, partials then reduce+bias
        gemm3_kernel<false, false><<<dim3(4, 24, 4), 256>>>(
            phh, phl, pw2h + (size_t)i * HH * DFF, pw2l + (size_t)i * HH * DFF,
            nullptr, ppart, nullptr, nullptr,
            ROWS, HH, DFF, DFF, 512, 512, 0, (size_t)ROWS * HH);
        reduce4_kernel<<<(ROWS * HH) / 256, 256>>>(ppart, b2 + (size_t)i * HH, psa);
        ln_kernel<<<ROWS, HH>>>(px, psa, ln2g + i * HH, ln2b + i * HH, pxh, pxl);
    }

    // factored aggregate MLP: U = actions @ Wa1[:, :H]^T + ba1 ; V2 = x @ Wa1[:, H:]^T
    gemm3_kernel<false, false><<<dim3(4, 128, 1), 256>>>(
        pacth, pactl, pwa1h, pwa1l, ba1, pU, nullptr, nullptr,
        AROWS, HH, HH, 2 * HH, HH, 0, 0, 0);
    gemm3_kernel<false, false><<<dim3(4, 24, 1), 256>>>(
        pxh, pxl, pwa1h + HH, pwa1l + HH, nullptr, pV2, nullptr, nullptr,
        ROWS, HH, HH, 2 * HH, HH, 0, 0, 0);

    aggregate_kernel<<<AROWS, HH>>>(pU, pV2, px, Wa2, ba2, amask, smask, psf, psfh, psfl);
    sfm_kernel<<<BB, HH>>>(psf, amask, psfm);

    // bilinear head: aw[l] = sf @ Wlab[l]^T (batched over z)
    gemm3_kernel<false, false><<<dim3(4, 128, NLL), 256>>>(
        psfh, psfl, pwlabh, pwlabl, nullptr, paw, nullptr, nullptr,
        AROWS, HH, HH, HH, HH, 0, (size_t)HH * HH, (size_t)AROWS * HH);

    adv_kernel<<<dim3(AROWS, NLL), HH>>>(paw, actions, blab, padv);
    val_kernel<<<BB, HH>>>(psfm, Wv, bv, pval);
    final_kernel<<<BB, 128>>>(padv, pval, out);
}

// round 12
// speedup vs baseline: 1.5770x; 1.0295x over previous
#include <cuda_runtime.h>
#include <cuda_bf16.h>
#include <cuda_pipeline.h>
#include <mma.h>
#include <math.h>

#define BB   512
#define SS   6
#define S2D  32
#define HH   256
#define NHH  8
#define DFF  2048
#define NLL  3
#define ROWS  (BB*SS)
#define AROWS (BB*S2D)
#define PITCH 40
#define TILEH (128*PITCH)

using namespace nvcuda;

// fp32 scratch
__device__ float g_x[ROWS*HH];
__device__ float g_qkv[ROWS*3*HH];
__device__ float g_sa[ROWS*HH];
__device__ float g_U[AROWS*HH];
__device__ float g_V2[ROWS*HH];
__device__ float g_sf[AROWS*HH];
__device__ float g_sfm[BB*HH];
__device__ float g_aw[(size_t)NLL*AROWS*HH];
__device__ float g_adv[AROWS*NLL];
__device__ float g_val[BB];
__device__ float g_part[4*ROWS*HH];

// bf16 hi/lo activation copies
__device__ __nv_bfloat16 g_xh[ROWS*HH],     g_xl[ROWS*HH];
__device__ __nv_bfloat16 g_ctxh[ROWS*HH],   g_ctxl[ROWS*HH];
__device__ __nv_bfloat16 g_hh[ROWS*DFF],    g_hl[ROWS*DFF];
__device__ __nv_bfloat16 g_acth[AROWS*HH],  g_actl[AROWS*HH];
__device__ __nv_bfloat16 g_sfh[AROWS*HH],   g_sfl[AROWS*HH];

// bf16 hi/lo weight copies
__device__ __nv_bfloat16 g_wqkvh[3*3*HH*HH], g_wqkvl[3*3*HH*HH];
__device__ __nv_bfloat16 g_woh[3*HH*HH],     g_wol[3*HH*HH];
__device__ __nv_bfloat16 g_w1h[3*DFF*HH],    g_w1l[3*DFF*HH];
__device__ __nv_bfloat16 g_w2h[3*HH*DFF],    g_w2l[3*HH*DFF];
__device__ __nv_bfloat16 g_wa1h[HH*2*HH],    g_wa1l[HH*2*HH];
__device__ __nv_bfloat16 g_wlabh[NLL*HH*HH], g_wlabl[NLL*HH*HH];

__device__ __forceinline__ float block_reduce_sum(float v)
{
    __shared__ float sm[33];
    int lane = threadIdx.x & 31;
    int wid = threadIdx.x >> 5;
    __syncthreads();
    #pragma unroll
    for (int o = 16; o; o >>= 1) v += __shfl_down_sync(0xffffffffu, v, o);
    if (lane == 0) sm[wid] = v;
    __syncthreads();
    int nw = (blockDim.x + 31) >> 5;
    v = (threadIdx.x < nw) ? sm[threadIdx.x] : 0.f;
    if (wid == 0) {
        #pragma unroll
        for (int o = 16; o; o >>= 1) v += __shfl_down_sync(0xffffffffu, v, o);
        if (lane == 0) sm[32] = v;
    }
    __syncthreads();
    return sm[32];
}

__device__ __forceinline__ void cvt_hilo(float x, __nv_bfloat16& h, __nv_bfloat16& l)
{
    h = __float2bfloat16(x);
    l = __float2bfloat16(x - __bfloat162float(h));
}

// vectorized fp32 -> (hi, lo) bf16 ; n multiple of 4
__global__ void cvt_kernel(const float* __restrict__ in,
                           __nv_bfloat16* __restrict__ h,
                           __nv_bfloat16* __restrict__ l, int n4)
{
    int i = blockIdx.x * 256 + threadIdx.x;
    if (i < n4) {
        float4 v = ((const float4*)in)[i];
        __nv_bfloat16 h0, h1, h2, h3, l0, l1, l2, l3;
        cvt_hilo(v.x, h0, l0);
        cvt_hilo(v.y, h1, l1);
        cvt_hilo(v.z, h2, l2);
        cvt_hilo(v.w, h3, l3);
        __nv_bfloat162* hp = (__nv_bfloat162*)(h + i * 4);
        __nv_bfloat162* lp = (__nv_bfloat162*)(l + i * 4);
        hp[0] = __halves2bfloat162(h0, h1);
        hp[1] = __halves2bfloat162(h2, h3);
        lp[0] = __halves2bfloat162(l0, l1);
        lp[1] = __halves2bfloat162(l2, l3);
    }
}

__global__ void add_pe_kernel(const float* __restrict__ states, float* __restrict__ x,
                              __nv_bfloat16* __restrict__ xh, __nv_bfloat16* __restrict__ xl)
{
    int row = blockIdx.x;
    int e = threadIdx.x;
    int n = row - (row / SS) * SS;
    int p = e >> 1;
    float dv = expf(-(float)(2 * p) * (9.210340371976184f / 256.f));
    float ang = (float)n * dv;
    float pe = (e & 1) ? cosf(ang) : sinf(ang);
    size_t idx = (size_t)row * HH + e;
    float v = states[idx] + pe;
    x[idx] = v;
    __nv_bfloat16 hh, ll;
    cvt_hilo(v, hh, ll);
    xh[idx] = hh;
    xl[idx] = ll;
}

// bf16x3 WMMA GEMM, pre-split inputs, cp.async 2-stage pipeline.
// C[M,N] = A @ B^T ; A row-major (lda), B [N,ldb] row-major.
// Block tile 128x128, BK=32, 8 warps (2m x 4n), warp tile 64x32.
// Dynamic smem: 4 matrices x 2 stages x 128*PITCH halves = 80KB.
// blockIdx.z: k-split chunk (kPerZ>0) or batched B/C (strideBz/strideCz).
template<bool RELU, bool OUTBF16>
__global__ __launch_bounds__(256) void gemm3_kernel(
    const __nv_bfloat16* __restrict__ Ahg, const __nv_bfloat16* __restrict__ Alg,
    const __nv_bfloat16* __restrict__ Bhg, const __nv_bfloat16* __restrict__ Blg,
    const float* __restrict__ bias, float* __restrict__ C,
    __nv_bfloat16* __restrict__ Ch, __nv_bfloat16* __restrict__ Cl,
    int M, int N, int lda, int ldb, int kLen, int kPerZ,
    size_t strideBz, size_t strideCz)
{
    extern __shared__ __nv_bfloat16 dyn[];
    __nv_bfloat16* Ahs = dyn;
    __nv_bfloat16* Als = Ahs + 2 * TILEH;
    __nv_bfloat16* Bhs = Als + 2 * TILEH;
    __nv_bfloat16* Bls = Bhs + 2 * TILEH;

    const __nv_bfloat16* Bh_p = Bhg + (size_t)blockIdx.z * strideBz;
    const __nv_bfloat16* Bl_p = Blg + (size_t)blockIdx.z * strideBz;
    size_t coff = (size_t)blockIdx.z * strideCz;
    int kOff = blockIdx.z * kPerZ;

    int m0 = blockIdx.y * 128;
    int n0 = blockIdx.x * 128;
    int t = threadIdx.x;
    int warp = t >> 5;
    int lane = t & 31;
    int wm = warp >> 2;       // 0..1  (64 rows each)
    int wn = warp & 3;        // 0..3  (32 cols each)

    // per-thread load coords: 512 float4-ops per matrix per stage, 2 per thread
    int r1 = t >> 1;              // 0..127
    int c1 = (t & 1) * 16;        // 0 or 16  -> two 8-half chunks below
    // use (id = t, t+256): id>>2 row, (id&3)*8 col
    int ra = t >> 2;
    int ca = (t & 3) * 8;
    int rb = (t + 256) >> 2;
    int cb = ((t + 256) & 3) * 8;
    (void)r1; (void)c1;

    int NK = kLen / 32;

    // prologue: stage 0
    {
        int gk = kOff;
        __pipeline_memcpy_async(&Ahs[ra * PITCH + ca], &Ahg[(size_t)(m0 + ra) * lda + gk + ca], 16);
        __pipeline_memcpy_async(&Ahs[rb * PITCH + cb], &Ahg[(size_t)(m0 + rb) * lda + gk + cb], 16);
        __pipeline_memcpy_async(&Als[ra * PITCH + ca], &Alg[(size_t)(m0 + ra) * lda + gk + ca], 16);
        __pipeline_memcpy_async(&Als[rb * PITCH + cb], &Alg[(size_t)(m0 + rb) * lda + gk + cb], 16);
        __pipeline_memcpy_async(&Bhs[ra * PITCH + ca], &Bh_p[(size_t)(n0 + ra) * ldb + gk + ca], 16);
        __pipeline_memcpy_async(&Bhs[rb * PITCH + cb], &Bh_p[(size_t)(n0 + rb) * ldb + gk + cb], 16);
        __pipeline_memcpy_async(&Bls[ra * PITCH + ca], &Bl_p[(size_t)(n0 + ra) * ldb + gk + ca], 16);
        __pipeline_memcpy_async(&Bls[rb * PITCH + cb], &Bl_p[(size_t)(n0 + rb) * ldb + gk + cb], 16);
        __pipeline_commit();
    }

    wmma::fragment<wmma::accumulator, 16, 16, 16, float> acc[4][2];
    #pragma unroll
    for (int mt = 0; mt < 4; mt++)
        #pragma unroll
        for (int nt = 0; nt < 2; nt++)
            wmma::fill_fragment(acc[mt][nt], 0.f);

    for (int kt = 0; kt < NK; kt++) {
        int cur = (kt & 1) * TILEH;
        if (kt + 1 < NK) {
            int nxt = ((kt + 1) & 1) * TILEH;
            int gk = kOff + (kt + 1) * 32;
            __pipeline_memcpy_async(&Ahs[nxt + ra * PITCH + ca], &Ahg[(size_t)(m0 + ra) * lda + gk + ca], 16);
            __pipeline_memcpy_async(&Ahs[nxt + rb * PITCH + cb], &Ahg[(size_t)(m0 + rb) * lda + gk + cb], 16);
            __pipeline_memcpy_async(&Als[nxt + ra * PITCH + ca], &Alg[(size_t)(m0 + ra) * lda + gk + ca], 16);
            __pipeline_memcpy_async(&Als[nxt + rb * PITCH + cb], &Alg[(size_t)(m0 + rb) * lda + gk + cb], 16);
            __pipeline_memcpy_async(&Bhs[nxt + ra * PITCH + ca], &Bh_p[(size_t)(n0 + ra) * ldb + gk + ca], 16);
            __pipeline_memcpy_async(&Bhs[nxt + rb * PITCH + cb], &Bh_p[(size_t)(n0 + rb) * ldb + gk + cb], 16);
            __pipeline_memcpy_async(&Bls[nxt + ra * PITCH + ca], &Bl_p[(size_t)(n0 + ra) * ldb + gk + ca], 16);
            __pipeline_memcpy_async(&Bls[nxt + rb * PITCH + cb], &Bl_p[(size_t)(n0 + rb) * ldb + gk + cb], 16);
            __pipeline_commit();
            __pipeline_wait_prior(1);
        } else {
            __pipeline_wait_prior(0);
        }
        __syncthreads();

        #pragma unroll
        for (int kk = 0; kk < 32; kk += 16) {
            wmma::fragment<wmma::matrix_a, 16, 16, 16, __nv_bfloat16, wmma::row_major> fah[4], fal[4];
            wmma::fragment<wmma::matrix_b, 16, 16, 16, __nv_bfloat16, wmma::col_major> fbh[2], fbl[2];
            #pragma unroll
            for (int mt = 0; mt < 4; mt++) {
                int ar = wm * 64 + mt * 16;
                wmma::load_matrix_sync(fah[mt], &Ahs[cur + ar * PITCH + kk], PITCH);
                wmma::load_matrix_sync(fal[mt], &Als[cur + ar * PITCH + kk], PITCH);
            }
            #pragma unroll
            for (int nt = 0; nt < 2; nt++) {
                int br = wn * 32 + nt * 16;
                wmma::load_matrix_sync(fbh[nt], &Bhs[cur + br * PITCH + kk], PITCH);
                wmma::load_matrix_sync(fbl[nt], &Bls[cur + br * PITCH + kk], PITCH);
            }
            #pragma unroll
            for (int mt = 0; mt < 4; mt++) {
                #pragma unroll
                for (int nt = 0; nt < 2; nt++) {
                    wmma::mma_sync(acc[mt][nt], fah[mt], fbh[nt], acc[mt][nt]);
                    wmma::mma_sync(acc[mt][nt], fah[mt], fbl[nt], acc[mt][nt]);
                    wmma::mma_sync(acc[mt][nt], fal[mt], fbh[nt], acc[mt][nt]);
                }
            }
        }
        __syncthreads();
    }

    // epilogue: reuse smem as fp32 staging (all pipeline reads done)
    float* Stage = (float*)dyn + (size_t)warp * (16 * 20);
    #pragma unroll
    for (int mt = 0; mt < 4; mt++) {
        #pragma unroll
        for (int nt = 0; nt < 2; nt++) {
            wmma::store_matrix_sync(Stage, acc[mt][nt], 20, wmma::mem_row_major);
            __syncwarp();
            #pragma unroll
            for (int e = 0; e < 8; e++) {
                int idx = e * 32 + lane;
                int r = idx >> 4;
                int c = idx & 15;
                int row = m0 + wm * 64 + mt * 16 + r;
                int col = n0 + wn * 32 + nt * 16 + c;
                float v = Stage[r * 20 + c];
                if (bias) v += bias[col];
                if (RELU) v = fmaxf(v, 0.f);
                size_t oidx = coff + (size_t)row * N + col;
                if (OUTBF16) {
                    __nv_bfloat16 hh, ll;
                    cvt_hilo(v, hh, ll);
                    Ch[oidx] = hh;
                    Cl[oidx] = ll;
                } else {
                    C[oidx] = v;
                }
            }
            __syncwarp();
        }
    }
}

// reduce 4 split-K partials + bias
__global__ void reduce4_kernel(const float* __restrict__ part, const float* __restrict__ bias,
                               float* __restrict__ outp)
{
    int i = blockIdx.x * 256 + threadIdx.x;
    int col = i & (HH - 1);
    const int MN = ROWS * HH;
    float v = part[i] + part[i + MN] + part[i + 2 * MN] + part[i + 3 * MN] + bias[col];
    outp[i] = v;
}

__global__ __launch_bounds__(128) void attn_kernel(const float* __restrict__ qkv,
                                                   __nv_bfloat16* __restrict__ ctxh,
                                                   __nv_bfloat16* __restrict__ ctxl)
{
    __shared__ __align__(16) float Ks[128 * 32];
    __shared__ __align__(16) float Vs[128 * 32];
    int n = blockIdx.x >> 3;
    int h = blockIdx.x & 7;
    int l = blockIdx.y * 128 + threadIdx.x;
    int qoff = h * 32;

    float q[32];
    {
        const float* qr = qkv + (size_t)(l * SS + n) * (3 * HH) + qoff;
        #pragma unroll
        for (int j = 0; j < 8; j++) {
            float4 v = *(const float4*)(qr + j * 4);
            q[j * 4 + 0] = v.x;
            q[j * 4 + 1] = v.y;
            q[j * 4 + 2] = v.z;
            q[j * 4 + 3] = v.w;
        }
    }

    float rm = -1e30f;
    float rs = 0.f;
    float acc[32];
    #pragma unroll
    for (int d = 0; d < 32; d++) acc[d] = 0.f;

    for (int m0 = 0; m0 < BB; m0 += 128) {
        __syncthreads();
        for (int i = threadIdx.x; i < 128 * 8; i += 128) {
            int mm = i >> 3;
            int j = i & 7;
            const float* base = qkv + (size_t)((m0 + mm) * SS + n) * (3 * HH) + qoff;
            *(float4*)&Ks[mm * 32 + j * 4] = *(const float4*)(base + HH + j * 4);
            *(float4*)&Vs[mm * 32 + j * 4] = *(const float4*)(base + 2 * HH + j * 4);
        }
        __syncthreads();
        for (int mm = 0; mm < 128; mm++) {
            float s = 0.f;
            #pragma unroll
            for (int d = 0; d < 32; d++) s = fmaf(q[d], Ks[mm * 32 + d], s);
            s *= 0.17677669529663687f;
            if (s > rm) {
                float f = __expf(rm - s);
                rs *= f;
                #pragma unroll
                for (int d = 0; d < 32; d++) acc[d] *= f;
                rm = s;
            }
            float p = __expf(s - rm);
            rs += p;
            #pragma unroll
            for (int d = 0; d < 32; d++) acc[d] = fmaf(p, Vs[mm * 32 + d], acc[d]);
        }
    }
    float inv = 1.f / rs;
    size_t obase = (size_t)(l * SS + n) * HH + qoff;
    #pragma unroll
    for (int d = 0; d < 32; d++) {
        __nv_bfloat16 hh, ll;
        cvt_hilo(acc[d] * inv, hh, ll);
        ctxh[obase + d] = hh;
        ctxl[obase + d] = ll;
    }
}

__global__ void ln_kernel(float* __restrict__ x, const float* __restrict__ delta,
                          const float* __restrict__ g, const float* __restrict__ b,
                          __nv_bfloat16* __restrict__ xh, __nv_bfloat16* __restrict__ xl)
{
    int row = blockIdx.x;
    int j = threadIdx.x;
    size_t idx = (size_t)row * HH + j;
    float v = x[idx] + delta[idx];
    float mu = block_reduce_sum(v) * (1.f / HH);
    float d = v - mu;
    float var = block_reduce_sum(d * d) * (1.f / HH);
    float o = d * rsqrtf(var + 1e-5f) * g[j] + b[j];
    x[idx] = o;
    __nv_bfloat16 hh, ll;
    cvt_hilo(o, hh, ll);
    xh[idx] = hh;
    xl[idx] = ll;
}

__global__ __launch_bounds__(256) void aggregate_kernel(
    const float* __restrict__ U, const float* __restrict__ V2,
    const float* __restrict__ outx, const float* __restrict__ Wa2,
    const float* __restrict__ ba2, const float* __restrict__ amask,
    const float* __restrict__ smask, float* __restrict__ sf,
    __nv_bfloat16* __restrict__ sfh, __nv_bfloat16* __restrict__ sfl)
{
    int b = blockIdx.x >> 5;
    int h = threadIdx.x;
    __shared__ float V2s[SS * HH];
    __shared__ float red[SS][8];
    __shared__ float wsh[SS];
    for (int i = h; i < SS * HH; i += 256) V2s[i] = V2[(size_t)b * SS * HH + i];
    __syncthreads();
    float u = U[(size_t)blockIdx.x * HH + h];
    float w2 = Wa2[h];
    float part[SS];
    #pragma unroll
    for (int k = 0; k < SS; k++) part[k] = w2 * fmaxf(u + V2s[k * HH + h], 0.f);
    int lane = h & 31;
    int wid = h >> 5;
    #pragma unroll
    for (int k = 0; k < SS; k++) {
        float v = part[k];
        #pragma unroll
        for (int o = 16; o; o >>= 1) v += __shfl_down_sync(0xffffffffu, v, o);
        if (lane == 0) red[k][wid] = v;
    }
    __syncthreads();
    if (h < SS) {
        float s = 0.f;
        #pragma unroll
        for (int w = 0; w < 8; w++) s += red[h][w];
        float a = fmaxf(s + ba2[0], 0.f);
        float m = amask[blockIdx.x] * smask[b * SS + h];
        wsh[h] = (m > 0.f) ? __expf(a) : 0.f;
    }
    __syncthreads();
    float denom = wsh[0] + wsh[1] + wsh[2] + wsh[3] + wsh[4] + wsh[5];
    denom = fmaxf(denom, 2e-15f);
    float acc = 0.f;
    #pragma unroll
    for (int k = 0; k < SS; k++) acc = fmaf(wsh[k], outx[(size_t)(b * SS + k) * HH + h], acc);
    float o = acc / denom;
    size_t oidx = (size_t)blockIdx.x * HH + h;
    sf[oidx] = o;
    __nv_bfloat16 hh, ll;
    cvt_hilo(o, hh, ll);
    sfh[oidx] = hh;
    sfl[oidx] = ll;
}

__global__ void sfm_kernel(const float* __restrict__ sf, const float* __restrict__ amask,
                           float* __restrict__ sfm)
{
    int b = blockIdx.x;
    int j = threadIdx.x;
    float an = 0.f;
    for (int s = 0; s < S2D; s++) an += amask[b * S2D + s];
    float acc = 0.f;
    for (int s = 0; s < S2D; s++) acc += sf[(size_t)(b * S2D + s) * HH + j];
    sfm[(size_t)b * HH + j] = acc / an;
}

__global__ void adv_kernel(const float* __restrict__ aw, const float* __restrict__ actions,
                           const float* __restrict__ blab, float* __restrict__ adv)
{
    int row = blockIdx.x;
    int l = blockIdx.y;
    float v = aw[((size_t)l * AROWS + row) * HH + threadIdx.x] *
              actions[(size_t)row * HH + threadIdx.x];
    float s = block_reduce_sum(v);
    if (threadIdx.x == 0) adv[(size_t)row * NLL + l] = s + blab[l];
}

__global__ void val_kernel(const float* __restrict__ sfm, const float* __restrict__ Wv,
                           const float* __restrict__ bv, float* __restrict__ val)
{
    int b = blockIdx.x;
    float v = sfm[(size_t)b * HH + threadIdx.x] * Wv[threadIdx.x];
    float s = block_reduce_sum(v);
    if (threadIdx.x == 0) val[b] = s + bv[0];
}

__global__ void final_kernel(const float* __restrict__ adv, const float* __restrict__ val,
                             float* __restrict__ out)
{
    int b = blockIdx.x;
    int t = threadIdx.x;
    float v = (t < S2D * NLL) ? adv[(size_t)b * S2D * NLL + t] : 0.f;
    float mean = block_reduce_sum(v) * (1.f / (S2D * NLL));
    if (t < S2D * NLL)
        out[(size_t)b * S2D * NLL + t] = val[b] + adv[(size_t)b * S2D * NLL + t] - mean;
}

#define GEMM_SMEM (8 * TILEH * 2)   /* bytes: 8 stage-matrices of 128*PITCH halves */

extern "C" void kernel_launch(void* const* d_in, const int* in_sizes, int n_in,
                              void* d_out, int out_size)
{
    const float* states  = (const float*)d_in[0];
    const float* smask   = (const float*)d_in[1];
    const float* actions = (const float*)d_in[2];
    const float* amask   = (const float*)d_in[3];
    const float* Wqkv    = (const float*)d_in[4];
    const float* bqkv    = (const float*)d_in[5];
    const float* Wo      = (const float*)d_in[6];
    const float* bo      = (const float*)d_in[7];
    const float* ln1g    = (const float*)d_in[8];
    const float* ln1b    = (const float*)d_in[9];
    const float* W1      = (const float*)d_in[10];
    const float* b1      = (const float*)d_in[11];
    const float* W2      = (const float*)d_in[12];
    const float* b2      = (const float*)d_in[13];
    const float* ln2g    = (const float*)d_in[14];
    const float* ln2b    = (const float*)d_in[15];
    const float* Wa1     = (const float*)d_in[16];
    const float* ba1     = (const float*)d_in[17];
    const float* Wa2     = (const float*)d_in[18];
    const float* ba2     = (const float*)d_in[19];
    const float* Wv      = (const float*)d_in[20];
    const float* bv      = (const float*)d_in[21];
    const float* Wlab    = (const float*)d_in[22];
    const float* blab    = (const float*)d_in[23];
    float* out = (float*)d_out;

    static int smem_set = 0;
    if (!smem_set) {
        cudaFuncSetAttribute(gemm3_kernel<false, false>,
                             cudaFuncAttributeMaxDynamicSharedMemorySize, GEMM_SMEM);
        cudaFuncSetAttribute(gemm3_kernel<true, true>,
                             cudaFuncAttributeMaxDynamicSharedMemorySize, GEMM_SMEM);
        smem_set = 1;
    }

    float *px, *pqkv, *psa, *pU, *pV2, *psf, *psfm, *paw, *padv, *pval, *ppart;
    cudaGetSymbolAddress((void**)&px,    g_x);
    cudaGetSymbolAddress((void**)&pqkv,  g_qkv);
    cudaGetSymbolAddress((void**)&psa,   g_sa);
    cudaGetSymbolAddress((void**)&pU,    g_U);
    cudaGetSymbolAddress((void**)&pV2,   g_V2);
    cudaGetSymbolAddress((void**)&psf,   g_sf);
    cudaGetSymbolAddress((void**)&psfm,  g_sfm);
    cudaGetSymbolAddress((void**)&paw,   g_aw);
    cudaGetSymbolAddress((void**)&padv,  g_adv);
    cudaGetSymbolAddress((void**)&pval,  g_val);
    cudaGetSymbolAddress((void**)&ppart, g_part);

    __nv_bfloat16 *pxh, *pxl, *pctxh, *pctxl, *phh, *phl, *pacth, *pactl, *psfh, *psfl;
    __nv_bfloat16 *pwqkvh, *pwqkvl, *pwoh, *pwol, *pw1h, *pw1l, *pw2h, *pw2l;
    __nv_bfloat16 *pwa1h, *pwa1l, *pwlabh, *pwlabl;
    cudaGetSymbolAddress((void**)&pxh,    g_xh);
    cudaGetSymbolAddress((void**)&pxl,    g_xl);
    cudaGetSymbolAddress((void**)&pctxh,  g_ctxh);
    cudaGetSymbolAddress((void**)&pctxl,  g_ctxl);
    cudaGetSymbolAddress((void**)&phh,    g_hh);
    cudaGetSymbolAddress((void**)&phl,    g_hl);
    cudaGetSymbolAddress((void**)&pacth,  g_acth);
    cudaGetSymbolAddress((void**)&pactl,  g_actl);
    cudaGetSymbolAddress((void**)&psfh,   g_sfh);
    cudaGetSymbolAddress((void**)&psfl,   g_sfl);
    cudaGetSymbolAddress((void**)&pwqkvh, g_wqkvh);
    cudaGetSymbolAddress((void**)&pwqkvl, g_wqkvl);
    cudaGetSymbolAddress((void**)&pwoh,   g_woh);
    cudaGetSymbolAddress((void**)&pwol,   g_wol);
    cudaGetSymbolAddress((void**)&pw1h,   g_w1h);
    cudaGetSymbolAddress((void**)&pw1l,   g_w1l);
    cudaGetSymbolAddress((void**)&pw2h,   g_w2h);
    cudaGetSymbolAddress((void**)&pw2l,   g_w2l);
    cudaGetSymbolAddress((void**)&pwa1h,  g_wa1h);
    cudaGetSymbolAddress((void**)&pwa1l,  g_wa1l);
    cudaGetSymbolAddress((void**)&pwlabh, g_wlabh);
    cudaGetSymbolAddress((void**)&pwlabl, g_wlabl);

    {
        int n;
        n = 3 * 3 * HH * HH / 4;  cvt_kernel<<<(n + 255) / 256, 256>>>(Wqkv,    pwqkvh, pwqkvl, n);
        n = 3 * HH * HH / 4;      cvt_kernel<<<(n + 255) / 256, 256>>>(Wo,      pwoh,   pwol,   n);
        n = 3 * DFF * HH / 4;     cvt_kernel<<<(n + 255) / 256, 256>>>(W1,      pw1h,   pw1l,   n);
        n = 3 * HH * DFF / 4;     cvt_kernel<<<(n + 255) / 256, 256>>>(W2,      pw2h,   pw2l,   n);
        n = HH * 2 * HH / 4;      cvt_kernel<<<(n + 255) / 256, 256>>>(Wa1,     pwa1h,  pwa1l,  n);
        n = NLL * HH * HH / 4;    cvt_kernel<<<(n + 255) / 256, 256>>>(Wlab,    pwlabh, pwlabl, n);
        n = AROWS * HH / 4;       cvt_kernel<<<(n + 255) / 256, 256>>>(actions, pacth,  pactl,  n);
    }

    add_pe_kernel<<<ROWS, HH>>>(states, px, pxh, pxl);

    for (int i = 0; i < 3; i++) {
        gemm3_kernel<false, false><<<dim3(6, 24, 1), 256, GEMM_SMEM>>>(
            pxh, pxl, pwqkvh + (size_t)i * 3 * HH * HH, pwqkvl + (size_t)i * 3 * HH * HH,
            bqkv + (size_t)i * 3 * HH, pqkv, nullptr, nullptr,
            ROWS, 3 * HH, HH, HH, HH, 0, 0, 0);
        attn_kernel<<<dim3(SS * NHH, BB / 128), 128>>>(pqkv, pctxh, pctxl);
        gemm3_kernel<false, false><<<dim3(2, 24, 1), 256, GEMM_SMEM>>>(
            pctxh, pctxl, pwoh + (size_t)i * HH * HH, pwol + (size_t)i * HH * HH,
            bo + (size_t)i * HH, psa, nullptr, nullptr,
            ROWS, HH, HH, HH, HH, 0, 0, 0);
        ln_kernel<<<ROWS, HH>>>(px, psa, ln1g + i * HH, ln1b + i * HH, pxh, pxl);
        gemm3_kernel<true, true><<<dim3(16, 24, 1), 256, GEMM_SMEM>>>(
            pxh, pxl, pw1h + (size_t)i * DFF * HH, pw1l + (size_t)i * DFF * HH,
            b1 + (size_t)i * DFF, nullptr, phh, phl,
            ROWS, DFF, HH, HH, HH, 0, 0, 0);
        gemm3_kernel<false, false><<<dim3(2, 24, 4), 256, GEMM_SMEM>>>(
            phh, phl, pw2h + (size_t)i * HH * DFF, pw2l + (size_t)i * HH * DFF,
            nullptr, ppart, nullptr, nullptr,
            ROWS, HH, DFF, DFF, 512, 512, 0, (size_t)ROWS * HH);
        reduce4_kernel<<<(ROWS * HH) / 256, 256>>>(ppart, b2 + (size_t)i * HH, psa);
        ln_kernel<<<ROWS, HH>>>(px, psa, ln2g + i * HH, ln2b + i * HH, pxh, pxl);
    }

    gemm3_kernel<false, false><<<dim3(2, 128, 1), 256, GEMM_SMEM>>>(
        pacth, pactl, pwa1h, pwa1l, ba1, pU, nullptr, nullptr,
        AROWS, HH, HH, 2 * HH, HH, 0, 0, 0);
    gemm3_kernel<false, false><<<dim3(2, 24, 1), 256, GEMM_SMEM>>>(
        pxh, pxl, pwa1h + HH, pwa1l + HH, nullptr, pV2, nullptr, nullptr,
        ROWS, HH, HH, 2 * HH, HH, 0, 0, 0);

    aggregate_kernel<<<AROWS, HH>>>(pU, pV2, px, Wa2, ba2, amask, smask, psf, psfh, psfl);
    sfm_kernel<<<BB, HH>>>(psf, amask, psfm);

    gemm3_kernel<false, false><<<dim3(2, 128, NLL), 256, GEMM_SMEM>>>(
        psfh, psfl, pwlabh, pwlabl, nullptr, paw, nullptr, nullptr,
        AROWS, HH, HH, HH, HH, 0, (size_t)HH * HH, (size_t)AROWS * HH);

    adv_kernel<<<dim3(AROWS, NLL), HH>>>(paw, actions, blab, padv);
    val_kernel<<<BB, HH>>>(psfm, Wv, bv, pval);
    final_kernel<<<BB, 128>>>(padv, pval, out);
}